// round 14
// baseline (speedup 1.0000x reference)
#include <cuda_runtime.h>
#include <cuda_fp16.h>
#include <math.h>
#include <stdint.h>

#define N_TOKENS 16384
#define D_MODEL  512
#define NQ       10
#define NL       2
#define DIM      1024
#define K2       2048   // C-build: 2-term split of K=1024

#define BM 128
#define BN 128
#define BKB 128                    // K bytes per stage (64 fp16)
#define NSTAGES 3
#define TILE_A (BM*BKB)            // 16 KB
#define TILE_Bb (BN*BKB)           // 16 KB
#define STAGE_B (TILE_A+TILE_Bb)   // 32 KB
#define SMEM_TOTAL (NSTAGES*STAGE_B)   // 96 KB -> 2 CTAs/SM
#define NTHREADS 128               // 4 warps, 2x2 grid of 64x64 warp tiles
#define NSPLIT 4                   // C-build split-K
#define NXPART 16                  // amp GEMM column tiles (2048/BN)

__device__ __align__(16) float  g_Ur[DIM*DIM];
__device__ __align__(16) float  g_Ui[DIM*DIM];
__device__ __align__(16) __half g_Us[2048*K2];          // U_stk split [h|l]
__device__ __align__(16) __half g_WinTs[D_MODEL*K2];    // Win^T dup [h|h]
__device__ __align__(16) float  g_Cf[NSPLIT*2048*D_MODEL]; // split-K partials
__device__ __align__(16) __half g_Cs[2048*D_MODEL];     // fp16(C) [2048,512]
__device__ __align__(16) float  g_d[2048];              // U_stk @ b_in
__device__ __align__(16) __half g_xs[N_TOKENS*D_MODEL]; // fp16(x)
__device__ __align__(16) __half g_Q[N_TOKENS*DIM];      // fp16(|amp|^2) unnorm
__device__ __align__(16) float  g_S[NXPART*N_TOKENS];   // per-row partial sums
__device__ __align__(16) __half g_Wouts[D_MODEL*DIM];   // fp16(W_out)
__device__ __align__(16) float  g_pre[N_TOKENS*D_MODEL];

// ---------------- PTX helpers (sm_80-era only; no 'a' features) --------------
__device__ __forceinline__ uint32_t smem_u32(const void* p) {
    return (uint32_t)__cvta_generic_to_shared(p);
}
#define CP16(saddr, gaddr) \
    asm volatile("cp.async.cg.shared.global [%0], [%1], 16;" \
                 :: "r"(saddr), "l"(gaddr) : "memory")
#define CP_COMMIT() asm volatile("cp.async.commit_group;" ::: "memory")
#define CP_WAIT1()  asm volatile("cp.async.wait_group 1;" ::: "memory")

#define LDSM4(r0,r1,r2,r3,addr) \
    asm volatile("ldmatrix.sync.aligned.m8n8.x4.shared.b16 {%0,%1,%2,%3}, [%4];" \
                 : "=r"(r0), "=r"(r1), "=r"(r2), "=r"(r3) : "r"(addr))

#define MMA16816(c, a0,a1,a2,a3, b0,b1) \
    asm volatile("mma.sync.aligned.m16n8k16.row.col.f32.f16.f16.f32 " \
                 "{%0,%1,%2,%3}, {%4,%5,%6,%7}, {%8,%9}, {%0,%1,%2,%3};" \
                 : "+f"((c)[0]), "+f"((c)[1]), "+f"((c)[2]), "+f"((c)[3]) \
                 : "r"(a0), "r"(a1), "r"(a2), "r"(a3), "r"(b0), "r"(b1))

#define SW128(off) ((off) ^ (((off) >> 3) & 0x70))

// ---- fp16 mma GEMM (128x128 tile, 64x64 warp tile, 128 thr, 2 CTAs/SM) ------
// (LOCKED: identical to R13 measured config)
template<int EPI>
__global__ __launch_bounds__(NTHREADS, 2)
void gemm_mma(const __half* __restrict__ A,
              const __half* __restrict__ B,
              float* __restrict__ C,
              __half* __restrict__ Q,
              float* __restrict__ Spart,
              const float* __restrict__ bias,
              int M, int N, int Ks, int Kfull)
{
    extern __shared__ char smem[];
    __shared__ float s_w[2][BM];
    const uint32_t S0 = smem_u32(smem);
    const int tid  = threadIdx.x;
    const int wid  = tid >> 5;
    const int lane = tid & 31;
    const int warp_m = (wid & 1) * 64;
    const int warp_n = (wid >> 1) * 64;
    const int m0 = blockIdx.y * BM;
    const int n0 = blockIdx.x * BN;
    const int nks = Ks / 64;

    const size_t ldb = (size_t)Kfull * 2;
    const size_t koff = (size_t)blockIdx.z * Ks * 2;
    const size_t Ab = (size_t)__cvta_generic_to_global(A) + (size_t)m0 * ldb + koff;
    const size_t Bb = (size_t)__cvta_generic_to_global(B) + (size_t)n0 * ldb + koff;

    const int a_row = (lane & 15);
    const int a_koff = (lane >> 4) << 4;
    const int b_row = (lane & 7) + ((lane >> 4) << 3);
    const int b_koff = ((lane >> 3) & 1) << 4;

    float c[4][8][4];
    #pragma unroll
    for (int mt = 0; mt < 4; mt++)
        #pragma unroll
        for (int nt = 0; nt < 8; nt++)
            #pragma unroll
            for (int j = 0; j < 4; j++) c[mt][nt][j] = 0.f;

    #pragma unroll
    for (int s = 0; s < NSTAGES - 1; s++) {
        const uint32_t saA = S0 + s * STAGE_B;
        const uint32_t saB = saA + TILE_A;
        const size_t ka = Ab + (size_t)s * BKB;
        const size_t kb = Bb + (size_t)s * BKB;
        #pragma unroll
        for (int i = 0; i < 16; i++) {
            int cc = tid + NTHREADS * i;
            if (cc < 1024) {
                int r = cc >> 3, p = (cc & 7) * 16;
                CP16(saA + SW128(r*128 + p), ka + (size_t)r * ldb + p);
            } else {
                int c2 = cc - 1024;
                int r = c2 >> 3, p = (c2 & 7) * 16;
                CP16(saB + SW128(r*128 + p), kb + (size_t)r * ldb + p);
            }
        }
        CP_COMMIT();
    }

    for (int ks = 0; ks < nks; ks++) {
        CP_WAIT1();
        __syncthreads();

        int ld = ks + NSTAGES - 1;
        if (ld < nks) {
            int slot = ld % NSTAGES;
            const uint32_t pA = S0 + slot * STAGE_B;
            const uint32_t pB = pA + TILE_A;
            const size_t ka = Ab + (size_t)ld * BKB;
            const size_t kb = Bb + (size_t)ld * BKB;
            #pragma unroll
            for (int i = 0; i < 16; i++) {
                int cc = tid + NTHREADS * i;
                if (cc < 1024) {
                    int r = cc >> 3, p = (cc & 7) * 16;
                    CP16(pA + SW128(r*128 + p), ka + (size_t)r * ldb + p);
                } else {
                    int c2 = cc - 1024;
                    int r = c2 >> 3, p = (c2 & 7) * 16;
                    CP16(pB + SW128(r*128 + p), kb + (size_t)r * ldb + p);
                }
            }
        }
        CP_COMMIT();

        const uint32_t saA = S0 + (ks % NSTAGES) * STAGE_B;
        const uint32_t saB = saA + TILE_A;
        #pragma unroll
        for (int kk = 0; kk < 4; kk++) {
            uint32_t a[4][4], b[4][4];
            #pragma unroll
            for (int mt = 0; mt < 4; mt++) {
                int r = warp_m + mt*16 + a_row;
                LDSM4(a[mt][0], a[mt][1], a[mt][2], a[mt][3],
                      saA + SW128(r*128 + kk*32 + a_koff));
            }
            #pragma unroll
            for (int nt2 = 0; nt2 < 4; nt2++) {
                int r = warp_n + nt2*16 + b_row;
                LDSM4(b[nt2][0], b[nt2][1], b[nt2][2], b[nt2][3],
                      saB + SW128(r*128 + kk*32 + b_koff));
            }
            #pragma unroll
            for (int mt = 0; mt < 4; mt++)
                #pragma unroll
                for (int nt = 0; nt < 8; nt++)
                    MMA16816(c[mt][nt],
                             a[mt][0], a[mt][1], a[mt][2], a[mt][3],
                             b[nt >> 1][(nt & 1) * 2],
                             b[nt >> 1][(nt & 1) * 2 + 1]);
        }
    }

    if (EPI == 0) {
        float* Cz = C + (size_t)blockIdx.z * M * N;
        #pragma unroll
        for (int mt = 0; mt < 4; mt++) {
            int r0 = m0 + warp_m + mt*16 + (lane >> 2);
            #pragma unroll
            for (int nt = 0; nt < 8; nt++) {
                int nn = n0 + warp_n + nt*8 + 2*(lane & 3);
                float b0 = bias ? bias[nn] : 0.f;
                float b1 = bias ? bias[nn+1] : 0.f;
                float2 v0 = make_float2(c[mt][nt][0] + b0, c[mt][nt][1] + b1);
                float2 v1 = make_float2(c[mt][nt][2] + b0, c[mt][nt][3] + b1);
                *(float2*)(Cz + (size_t)r0 * N + nn) = v0;
                *(float2*)(Cz + (size_t)(r0+8) * N + nn) = v1;
            }
        }
    } else {
        const int Nq = N >> 1;
        #pragma unroll
        for (int mt = 0; mt < 4; mt++) {
            int rl0 = warp_m + mt*16 + (lane >> 2);
            float sum0 = 0.f, sum1 = 0.f;
            #pragma unroll
            for (int nt = 0; nt < 8; nt++) {
                int nn = n0 + warp_n + nt*8 + 2*(lane & 3);
                float dr = bias[nn], di = bias[nn+1];
                float re0 = c[mt][nt][0] + dr, im0 = c[mt][nt][1] + di;
                float re1 = c[mt][nt][2] + dr, im1 = c[mt][nt][3] + di;
                float q0 = re0*re0 + im0*im0;
                float q1 = re1*re1 + im1*im1;
                int pcol = (nn >> 1);
                Q[(size_t)(m0 + rl0) * Nq + pcol]     = __float2half(q0);
                Q[(size_t)(m0 + rl0 + 8) * Nq + pcol] = __float2half(q1);
                sum0 += q0; sum1 += q1;
            }
            sum0 += __shfl_down_sync(0xffffffffu, sum0, 2);
            sum0 += __shfl_down_sync(0xffffffffu, sum0, 1);
            sum1 += __shfl_down_sync(0xffffffffu, sum1, 2);
            sum1 += __shfl_down_sync(0xffffffffu, sum1, 1);
            if ((lane & 3) == 0) {
                s_w[wid >> 1][rl0]     = sum0;
                s_w[wid >> 1][rl0 + 8] = sum1;
            }
        }
        __syncthreads();
        if (tid < BM) {
            Spart[(size_t)blockIdx.x * M + m0 + tid] = s_w[0][tid] + s_w[1][tid];
        }
    }
}

// ---------------- circuit unitary (512 threads: 1 butterfly/thread) -----------
__device__ __forceinline__ float2 cmul(float2 a, float2 b) {
    return make_float2(a.x*b.x - a.y*b.y, a.x*b.y + a.y*b.x);
}
__device__ __forceinline__ float2 cadd(float2 a, float2 b) {
    return make_float2(a.x + b.x, a.y + b.y);
}
__device__ __forceinline__ void split2h(float v, __half& h, __half& l) {
    h = __float2half(v);
    l = __float2half(v - __half2float(h));
}

__global__ __launch_bounds__(512)
void build_unitary(const float* __restrict__ rot,
                   const float* __restrict__ ent,
                   float* __restrict__ Ur, float* __restrict__ Ui) {
    __shared__ float2 st[DIM];
    const int j = blockIdx.x;
    const int t = threadIdx.x;   // 512 threads
    st[t]       = make_float2(t == j ? 1.f : 0.f, 0.f);
    st[t + 512] = make_float2((t + 512) == j ? 1.f : 0.f, 0.f);
    __syncthreads();
    for (int l = 0; l < NL; l++) {
        for (int q = 0; q < NQ; q++) {
            const float t1 = rot[(l*NQ + q)*3 + 0];
            const float t2 = rot[(l*NQ + q)*3 + 1];
            const float t3 = rot[(l*NQ + q)*3 + 2];
            float c1, s1; sincosf(0.5f*t1, &s1, &c1);
            float2 rx00 = {c1,0.f}, rx01 = {0.f,-s1}, rx10 = {0.f,-s1}, rx11 = {c1,0.f};
            float c2, s2; sincosf(0.5f*t2, &s2, &c2);
            float2 ry00 = {c2,0.f}, ry01 = {-s2,0.f}, ry10 = {s2,0.f}, ry11 = {c2,0.f};
            float2 a00 = cadd(cmul(ry00,rx00), cmul(ry01,rx10));
            float2 a01 = cadd(cmul(ry00,rx01), cmul(ry01,rx11));
            float2 a10 = cadd(cmul(ry10,rx00), cmul(ry11,rx10));
            float2 a11 = cadd(cmul(ry10,rx01), cmul(ry11,rx11));
            float cz, sz; sincosf(0.5f*t3, &sz, &cz);
            float2 ez0 = {cz,-sz}, ez1 = {cz,sz};
            float2 m00 = cmul(ez0,a00), m01 = cmul(ez0,a01);
            float2 m10 = cmul(ez1,a10), m11 = cmul(ez1,a11);
            const int mask = 1 << (NQ - 1 - q);
            int i0 = ((t & ~(mask-1)) << 1) | (t & (mask-1));
            int i1 = i0 | mask;
            float2 v0 = st[i0], v1 = st[i1];
            st[i0] = cadd(cmul(m00,v0), cmul(m01,v1));
            st[i1] = cadd(cmul(m10,v0), cmul(m11,v1));
            __syncthreads();
        }
        #pragma unroll
        for (int half = 0; half < 2; half++) {
            int i = t + half * 512;
            float ang = 0.f;
            #pragma unroll
            for (int g = 0; g < NQ-1; g++) {
                int b1 = (i >> (NQ-1-g)) & 1;
                int b2 = (i >> (NQ-2-g)) & 1;
                if (b1 & b2) ang += ent[l*(NQ-1) + g];
            }
            float sn, cs; sincosf(ang, &sn, &cs);
            st[i] = cmul(st[i], make_float2(cs, sn));
        }
        __syncthreads();
    }
    #pragma unroll
    for (int half = 0; half < 2; half++) {
        int i = t + half * 512;
        Ur[i*DIM + j] = st[i].x;
        Ui[i*DIM + j] = st[i].y;
    }
}

// ---------------- split / pack ---------------------------------------------------
// U_stk rows: 2j = Ur[j,:], 2j+1 = Ui[j,:]; split -> Us [2048, 2048] = [h|l]
__global__ void pack_Ustk(const float* __restrict__ Ur, const float* __restrict__ Ui,
                          __half* __restrict__ Us) {
    int i = blockIdx.x * blockDim.x + threadIdx.x;
    if (i >= 2048 * DIM) return;
    int n = i / DIM, k = i % DIM;
    int j = n >> 1;
    float v = (n & 1) ? Ui[(size_t)j*DIM + k] : Ur[(size_t)j*DIM + k];
    __half h, l; split2h(v, h, l);
    __half* row = Us + (size_t)n * K2;
    row[k] = h; row[1024 + k] = l;
}

// Win [1024(k),512(m)] -> WinTs [512(m), 2048] = [h|h] of Win^T (smem transpose)
__global__ void pack_WinT(const float* __restrict__ W, __half* __restrict__ Ws) {
    __shared__ float s[32][33];
    const int bm = blockIdx.x * 32;      // m tile
    const int bk = blockIdx.y * 32;      // k tile
    const int tx = threadIdx.x & 31;
    const int ty = threadIdx.x >> 5;     // 0..7
    #pragma unroll
    for (int jj = 0; jj < 4; jj++) {
        int k = bk + ty + 8*jj;
        s[ty + 8*jj][tx] = W[(size_t)k * D_MODEL + bm + tx];
    }
    __syncthreads();
    #pragma unroll
    for (int jj = 0; jj < 4; jj++) {
        int m = bm + ty + 8*jj;
        __half h = __float2half(s[tx][ty + 8*jj]);
        __half* row = Ws + (size_t)m * K2 + bk + tx;
        row[0] = h; row[1024] = h;
    }
}

// Cs = fp16(sum of NSPLIT partials)
__global__ void pack_Cs(const float* __restrict__ Cf, __half* __restrict__ Cs) {
    int i = blockIdx.x * blockDim.x + threadIdx.x;
    if (i >= 2048 * D_MODEL) return;
    float s = 0.f;
    #pragma unroll
    for (int z = 0; z < NSPLIT; z++) s += Cf[(size_t)z * 2048 * D_MODEL + i];
    Cs[i] = __float2half(s);
}

// d[n] = sum_k U_stk[n,k] * b_in[k]  (128 threads per row, deterministic)
__global__ __launch_bounds__(128)
void d_vec(const float* __restrict__ Ur, const float* __restrict__ Ui,
           const float* __restrict__ b_in, float* __restrict__ d) {
    __shared__ float sh[4];
    const int n = blockIdx.x;
    const int t = threadIdx.x;
    const int lane = t & 31, w = t >> 5;
    const int j = n >> 1;
    const float* row = (n & 1) ? Ui + (size_t)j*DIM : Ur + (size_t)j*DIM;
    float s = 0.f;
    #pragma unroll
    for (int i = 0; i < 8; i++) {
        int k = t + i * 128;
        s += row[k] * b_in[k];
    }
    #pragma unroll
    for (int o = 16; o > 0; o >>= 1) s += __shfl_down_sync(0xffffffffu, s, o);
    if (lane == 0) sh[w] = s;
    __syncthreads();
    if (t == 0) d[n] = (sh[0] + sh[1]) + (sh[2] + sh[3]);
}

__global__ void conv_x(const float* __restrict__ x, __half* __restrict__ xs) {
    int i = blockIdx.x * blockDim.x + threadIdx.x;
    int n = N_TOKENS * D_MODEL / 4;
    if (i >= n) return;
    float4 v = ((const float4*)x)[i];
    __half2 a; a.x = __float2half(v.x); a.y = __float2half(v.y);
    __half2 b; b.x = __float2half(v.z); b.y = __float2half(v.w);
    ((__half2*)xs)[2*i] = a;
    ((__half2*)xs)[2*i + 1] = b;
}

__global__ void conv_Wout(const float* __restrict__ W, __half* __restrict__ Ws) {
    int i = blockIdx.x * blockDim.x + threadIdx.x;
    int n = D_MODEL * DIM / 4;
    if (i >= n) return;
    float4 v = ((const float4*)W)[i];
    __half2 a; a.x = __float2half(v.x); a.y = __float2half(v.y);
    __half2 b; b.x = __float2half(v.z); b.y = __float2half(v.w);
    ((__half2*)Ws)[2*i] = a;
    ((__half2*)Ws)[2*i + 1] = b;
}

// ---------------- reductions ----------------------------------------------------
__device__ float blockReduceSum256(float v) {
    __shared__ float sh[8];
    __syncthreads();
    int lane = threadIdx.x & 31, wid = threadIdx.x >> 5;
    #pragma unroll
    for (int o = 16; o > 0; o >>= 1) v += __shfl_down_sync(0xffffffffu, v, o);
    if (lane == 0) sh[wid] = v;
    __syncthreads();
    float s = 0.f;
    if (threadIdx.x < 8) s = sh[threadIdx.x];
    if (wid == 0) {
        #pragma unroll
        for (int o = 4; o > 0; o >>= 1) s += __shfl_down_sync(0xffu, s, o);
        if (lane == 0) sh[0] = s;
    }
    __syncthreads();
    return sh[0];
}

// pre = preU/s + b_out, then LayerNorm -> out
__global__ void finalize(const float* __restrict__ preU,
                         const float* __restrict__ Spart,
                         const float* __restrict__ b_out,
                         const float* __restrict__ w, const float* __restrict__ b,
                         float* __restrict__ out) {
    const int row = blockIdx.x;
    const int t = threadIdx.x;
    float s = 0.f;
    #pragma unroll
    for (int c = 0; c < NXPART; c++) s += Spart[(size_t)c * N_TOKENS + row];
    float inv_s = 1.f / fmaxf(s, 1e-24f);
    const float* p = preU + (size_t)row * D_MODEL;
    float v0 = p[t] * inv_s + b_out[t];
    float v1 = p[t+256] * inv_s + b_out[t+256];
    float mu = blockReduceSum256(v0 + v1) * (1.f / D_MODEL);
    float d0 = v0 - mu, d1 = v1 - mu;
    float var = blockReduceSum256(d0*d0 + d1*d1) * (1.f / D_MODEL);
    float inv = rsqrtf(var + 1e-5f);
    float* o = out + (size_t)row * D_MODEL;
    o[t]     = d0 * inv * w[t]     + b[t];
    o[t+256] = d1 * inv * w[t+256] + b[t+256];
}

// ---------------- launch ---------------------------------------------------------
extern "C" void kernel_launch(void* const* d_in, const int* in_sizes, int n_in,
                              void* d_out, int out_size) {
    const float* x     = (const float*)d_in[0];
    const float* W_in  = (const float*)d_in[1];
    const float* b_in  = (const float*)d_in[2];
    const float* W_out = (const float*)d_in[3];
    const float* b_out = (const float*)d_in[4];
    const float* rot   = (const float*)d_in[5];
    const float* ent   = (const float*)d_in[6];
    const float* ln_w  = (const float*)d_in[7];
    const float* ln_b  = (const float*)d_in[8];
    float* out = (float*)d_out;

    float *Ur, *Ui, *Cf, *dv, *Sp, *pre;
    __half *Us, *WinTs, *Cs, *xs, *Q, *Wouts;
    cudaGetSymbolAddress((void**)&Ur,    g_Ur);
    cudaGetSymbolAddress((void**)&Ui,    g_Ui);
    cudaGetSymbolAddress((void**)&Us,    g_Us);
    cudaGetSymbolAddress((void**)&WinTs, g_WinTs);
    cudaGetSymbolAddress((void**)&Cf,    g_Cf);
    cudaGetSymbolAddress((void**)&Cs,    g_Cs);
    cudaGetSymbolAddress((void**)&dv,    g_d);
    cudaGetSymbolAddress((void**)&xs,    g_xs);
    cudaGetSymbolAddress((void**)&Q,     g_Q);
    cudaGetSymbolAddress((void**)&Sp,    g_S);
    cudaGetSymbolAddress((void**)&Wouts, g_Wouts);
    cudaGetSymbolAddress((void**)&pre,   g_pre);

    cudaFuncSetAttribute(gemm_mma<0>, cudaFuncAttributeMaxDynamicSharedMemorySize, SMEM_TOTAL);
    cudaFuncSetAttribute(gemm_mma<1>, cudaFuncAttributeMaxDynamicSharedMemorySize, SMEM_TOTAL);

    // 1) circuit unitary (512 threads: 1 butterfly per thread)
    build_unitary<<<DIM, 512>>>(rot, ent, Ur, Ui);

    // 2) packs for C-build (coalesced; WinT via smem transpose)
    pack_Ustk<<<(2048*DIM + 255)/256, 256>>>(Ur, Ui, Us);
    pack_WinT<<<dim3(D_MODEL/32, DIM/32), 256>>>(W_in, WinTs);

    // 3) C = U_stk @ Win [2048 x 512], split-K z=4 (Ks=512 each)
    gemm_mma<0><<<dim3(D_MODEL/BN, 2048/BM, NSPLIT), NTHREADS, SMEM_TOTAL>>>(
        Us, WinTs, Cf, nullptr, nullptr, nullptr, 2048, D_MODEL, K2/NSPLIT, K2);

    // 4) d = U_stk @ b_in ; Cs = fp16(sum Cf); xs = fp16(x); Wouts = fp16(W_out)
    d_vec<<<2048, 128>>>(Ur, Ui, b_in, dv);
    pack_Cs<<<(2048*D_MODEL + 255)/256, 256>>>(Cf, Cs);
    conv_x<<<(N_TOKENS*D_MODEL/4 + 255)/256, 256>>>(x, xs);
    conv_Wout<<<(D_MODEL*DIM/4 + 255)/256, 256>>>(W_out, Wouts);

    // 5) amp GEMM + fused |amp|^2 epilogue: Q fp16 [16384,1024] + row partials
    gemm_mma<1><<<dim3(2048/BN, N_TOKENS/BM, 1), NTHREADS, SMEM_TOTAL>>>(
        xs, Cs, nullptr, Q, Sp, dv, N_TOKENS, 2048, D_MODEL, D_MODEL);

    // 6) preU = Q @ fp16(W_out)^T (unnormalized, no bias)
    gemm_mma<0><<<dim3(D_MODEL/BN, N_TOKENS/BM, 1), NTHREADS, SMEM_TOTAL>>>(
        Q, Wouts, pre, nullptr, nullptr, nullptr, N_TOKENS, D_MODEL, DIM, DIM);

    // 7) finalize: pre/s + b_out, LayerNorm
    finalize<<<N_TOKENS, 256>>>(pre, Sp, b_out, ln_w, ln_b, out);
}

// round 15
// speedup vs baseline: 1.2562x; 1.2562x over previous
#include <cuda_runtime.h>
#include <cuda_fp16.h>
#include <math.h>
#include <stdint.h>

#define N_TOKENS 16384
#define D_MODEL  512
#define NQ       10
#define NL       2
#define DIM      1024

#define BM 128
#define BN 128
#define BKB 128                    // K bytes per stage (64 fp16)
#define NSTAGES 3
#define TILE_A (BM*BKB)            // 16 KB
#define TILE_Bb (BN*BKB)           // 16 KB
#define STAGE_B (TILE_A+TILE_Bb)   // 32 KB
#define SMEM_TOTAL (NSTAGES*STAGE_B)   // 96 KB -> 2 CTAs/SM
#define NTHREADS 128               // 4 warps, 2x2 grid of 64x64 warp tiles
#define NXPART 16                  // amp GEMM column tiles (2048/BN)

__device__ __align__(16) __half g_Cs[2048*D_MODEL];     // fp16(C) [2048,512]
__device__ __align__(16) float  g_d[2048];              // U_stk @ b_in
__device__ __align__(16) __half g_xs[N_TOKENS*D_MODEL]; // fp16(x)
__device__ __align__(16) __half g_Q[N_TOKENS*DIM];      // fp16(|amp|^2) unnorm
__device__ __align__(16) float  g_S[NXPART*N_TOKENS];   // per-row partial sums
__device__ __align__(16) __half g_Wouts[D_MODEL*DIM];   // fp16(W_out)
__device__ __align__(16) float  g_pre[N_TOKENS*D_MODEL];

// ---------------- PTX helpers (sm_80-era only; no 'a' features) --------------
__device__ __forceinline__ uint32_t smem_u32(const void* p) {
    return (uint32_t)__cvta_generic_to_shared(p);
}
#define CP16(saddr, gaddr) \
    asm volatile("cp.async.cg.shared.global [%0], [%1], 16;" \
                 :: "r"(saddr), "l"(gaddr) : "memory")
#define CP_COMMIT() asm volatile("cp.async.commit_group;" ::: "memory")
#define CP_WAIT1()  asm volatile("cp.async.wait_group 1;" ::: "memory")

#define LDSM4(r0,r1,r2,r3,addr) \
    asm volatile("ldmatrix.sync.aligned.m8n8.x4.shared.b16 {%0,%1,%2,%3}, [%4];" \
                 : "=r"(r0), "=r"(r1), "=r"(r2), "=r"(r3) : "r"(addr))

#define MMA16816(c, a0,a1,a2,a3, b0,b1) \
    asm volatile("mma.sync.aligned.m16n8k16.row.col.f32.f16.f16.f32 " \
                 "{%0,%1,%2,%3}, {%4,%5,%6,%7}, {%8,%9}, {%0,%1,%2,%3};" \
                 : "+f"((c)[0]), "+f"((c)[1]), "+f"((c)[2]), "+f"((c)[3]) \
                 : "r"(a0), "r"(a1), "r"(a2), "r"(a3), "r"(b0), "r"(b1))

#define SW128(off) ((off) ^ (((off) >> 3) & 0x70))

// ---- fp16 mma GEMM (128x128 tile, 64x64 warp tile, 128 thr, 2 CTAs/SM) ------
// (LOCKED: identical to R13 measured config)
// EPI=0: C[M,N] = A @ B^T + bias (fp32)
// EPI=1: cols are (re,im) pairs; q = (re+d)^2+(im+d')^2 -> Q fp16 [M, N/2];
//        deterministic per-row partial sums -> Spart[blockIdx.x*M + row].
template<int EPI>
__global__ __launch_bounds__(NTHREADS, 2)
void gemm_mma(const __half* __restrict__ A,
              const __half* __restrict__ B,
              float* __restrict__ C,
              __half* __restrict__ Q,
              float* __restrict__ Spart,
              const float* __restrict__ bias,
              int M, int N, int Ks, int Kfull)
{
    extern __shared__ char smem[];
    __shared__ float s_w[2][BM];
    const uint32_t S0 = smem_u32(smem);
    const int tid  = threadIdx.x;
    const int wid  = tid >> 5;
    const int lane = tid & 31;
    const int warp_m = (wid & 1) * 64;
    const int warp_n = (wid >> 1) * 64;
    const int m0 = blockIdx.y * BM;
    const int n0 = blockIdx.x * BN;
    const int nks = Ks / 64;

    const size_t ldb = (size_t)Kfull * 2;
    const size_t Ab = (size_t)__cvta_generic_to_global(A) + (size_t)m0 * ldb;
    const size_t Bb = (size_t)__cvta_generic_to_global(B) + (size_t)n0 * ldb;

    const int a_row = (lane & 15);
    const int a_koff = (lane >> 4) << 4;
    const int b_row = (lane & 7) + ((lane >> 4) << 3);
    const int b_koff = ((lane >> 3) & 1) << 4;

    float c[4][8][4];
    #pragma unroll
    for (int mt = 0; mt < 4; mt++)
        #pragma unroll
        for (int nt = 0; nt < 8; nt++)
            #pragma unroll
            for (int j = 0; j < 4; j++) c[mt][nt][j] = 0.f;

    #pragma unroll
    for (int s = 0; s < NSTAGES - 1; s++) {
        const uint32_t saA = S0 + s * STAGE_B;
        const uint32_t saB = saA + TILE_A;
        const size_t ka = Ab + (size_t)s * BKB;
        const size_t kb = Bb + (size_t)s * BKB;
        #pragma unroll
        for (int i = 0; i < 16; i++) {
            int cc = tid + NTHREADS * i;
            if (cc < 1024) {
                int r = cc >> 3, p = (cc & 7) * 16;
                CP16(saA + SW128(r*128 + p), ka + (size_t)r * ldb + p);
            } else {
                int c2 = cc - 1024;
                int r = c2 >> 3, p = (c2 & 7) * 16;
                CP16(saB + SW128(r*128 + p), kb + (size_t)r * ldb + p);
            }
        }
        CP_COMMIT();
    }

    for (int ks = 0; ks < nks; ks++) {
        CP_WAIT1();
        __syncthreads();

        int ld = ks + NSTAGES - 1;
        if (ld < nks) {
            int slot = ld % NSTAGES;
            const uint32_t pA = S0 + slot * STAGE_B;
            const uint32_t pB = pA + TILE_A;
            const size_t ka = Ab + (size_t)ld * BKB;
            const size_t kb = Bb + (size_t)ld * BKB;
            #pragma unroll
            for (int i = 0; i < 16; i++) {
                int cc = tid + NTHREADS * i;
                if (cc < 1024) {
                    int r = cc >> 3, p = (cc & 7) * 16;
                    CP16(pA + SW128(r*128 + p), ka + (size_t)r * ldb + p);
                } else {
                    int c2 = cc - 1024;
                    int r = c2 >> 3, p = (c2 & 7) * 16;
                    CP16(pB + SW128(r*128 + p), kb + (size_t)r * ldb + p);
                }
            }
        }
        CP_COMMIT();

        const uint32_t saA = S0 + (ks % NSTAGES) * STAGE_B;
        const uint32_t saB = saA + TILE_A;
        #pragma unroll
        for (int kk = 0; kk < 4; kk++) {
            uint32_t a[4][4], b[4][4];
            #pragma unroll
            for (int mt = 0; mt < 4; mt++) {
                int r = warp_m + mt*16 + a_row;
                LDSM4(a[mt][0], a[mt][1], a[mt][2], a[mt][3],
                      saA + SW128(r*128 + kk*32 + a_koff));
            }
            #pragma unroll
            for (int nt2 = 0; nt2 < 4; nt2++) {
                int r = warp_n + nt2*16 + b_row;
                LDSM4(b[nt2][0], b[nt2][1], b[nt2][2], b[nt2][3],
                      saB + SW128(r*128 + kk*32 + b_koff));
            }
            #pragma unroll
            for (int mt = 0; mt < 4; mt++)
                #pragma unroll
                for (int nt = 0; nt < 8; nt++)
                    MMA16816(c[mt][nt],
                             a[mt][0], a[mt][1], a[mt][2], a[mt][3],
                             b[nt >> 1][(nt & 1) * 2],
                             b[nt >> 1][(nt & 1) * 2 + 1]);
        }
    }

    if (EPI == 0) {
        #pragma unroll
        for (int mt = 0; mt < 4; mt++) {
            int r0 = m0 + warp_m + mt*16 + (lane >> 2);
            #pragma unroll
            for (int nt = 0; nt < 8; nt++) {
                int nn = n0 + warp_n + nt*8 + 2*(lane & 3);
                float b0 = bias ? bias[nn] : 0.f;
                float b1 = bias ? bias[nn+1] : 0.f;
                float2 v0 = make_float2(c[mt][nt][0] + b0, c[mt][nt][1] + b1);
                float2 v1 = make_float2(c[mt][nt][2] + b0, c[mt][nt][3] + b1);
                *(float2*)(C + (size_t)r0 * N + nn) = v0;
                *(float2*)(C + (size_t)(r0+8) * N + nn) = v1;
            }
        }
    } else {
        const int Nq = N >> 1;
        #pragma unroll
        for (int mt = 0; mt < 4; mt++) {
            int rl0 = warp_m + mt*16 + (lane >> 2);
            float sum0 = 0.f, sum1 = 0.f;
            #pragma unroll
            for (int nt = 0; nt < 8; nt++) {
                int nn = n0 + warp_n + nt*8 + 2*(lane & 3);
                float dr = bias[nn], di = bias[nn+1];
                float re0 = c[mt][nt][0] + dr, im0 = c[mt][nt][1] + di;
                float re1 = c[mt][nt][2] + dr, im1 = c[mt][nt][3] + di;
                float q0 = re0*re0 + im0*im0;
                float q1 = re1*re1 + im1*im1;
                int pcol = (nn >> 1);
                Q[(size_t)(m0 + rl0) * Nq + pcol]     = __float2half(q0);
                Q[(size_t)(m0 + rl0 + 8) * Nq + pcol] = __float2half(q1);
                sum0 += q0; sum1 += q1;
            }
            sum0 += __shfl_down_sync(0xffffffffu, sum0, 2);
            sum0 += __shfl_down_sync(0xffffffffu, sum0, 1);
            sum1 += __shfl_down_sync(0xffffffffu, sum1, 2);
            sum1 += __shfl_down_sync(0xffffffffu, sum1, 1);
            if ((lane & 3) == 0) {
                s_w[wid >> 1][rl0]     = sum0;
                s_w[wid >> 1][rl0 + 8] = sum1;
            }
        }
        __syncthreads();
        if (tid < BM) {
            Spart[(size_t)blockIdx.x * M + m0 + tid] = s_w[0][tid] + s_w[1][tid];
        }
    }
}

// ---- circuit sim applied directly to Win columns (and b_in) -----------------
// Block m < 512: psi0 = Win[:, m] -> writes Cs[2i][m]=re, Cs[2i+1][m]=im (fp16)
// Block m == 512: psi0 = b_in     -> writes d[2i]=re, d[2i+1]=im (fp32)
__device__ __forceinline__ float2 cmul(float2 a, float2 b) {
    return make_float2(a.x*b.x - a.y*b.y, a.x*b.y + a.y*b.x);
}
__device__ __forceinline__ float2 cadd(float2 a, float2 b) {
    return make_float2(a.x + b.x, a.y + b.y);
}

__global__ void sim_cols(const float* __restrict__ rot,
                         const float* __restrict__ ent,
                         const float* __restrict__ W_in,
                         const float* __restrict__ b_in,
                         __half* __restrict__ Cs, float* __restrict__ d) {
    __shared__ float2 st[DIM];
    const int m = blockIdx.x;   // 0..512
    const int t = threadIdx.x;  // 256 threads
    for (int i = t; i < DIM; i += 256) {
        float v = (m < D_MODEL) ? W_in[(size_t)i * D_MODEL + m] : b_in[i];
        st[i] = make_float2(v, 0.f);
    }
    __syncthreads();
    for (int l = 0; l < NL; l++) {
        for (int q = 0; q < NQ; q++) {
            const float t1 = rot[(l*NQ + q)*3 + 0];
            const float t2 = rot[(l*NQ + q)*3 + 1];
            const float t3 = rot[(l*NQ + q)*3 + 2];
            float c1, s1; sincosf(0.5f*t1, &s1, &c1);
            float2 rx00 = {c1,0.f}, rx01 = {0.f,-s1}, rx10 = {0.f,-s1}, rx11 = {c1,0.f};
            float c2, s2; sincosf(0.5f*t2, &s2, &c2);
            float2 ry00 = {c2,0.f}, ry01 = {-s2,0.f}, ry10 = {s2,0.f}, ry11 = {c2,0.f};
            float2 a00 = cadd(cmul(ry00,rx00), cmul(ry01,rx10));
            float2 a01 = cadd(cmul(ry00,rx01), cmul(ry01,rx11));
            float2 a10 = cadd(cmul(ry10,rx00), cmul(ry11,rx10));
            float2 a11 = cadd(cmul(ry10,rx01), cmul(ry11,rx11));
            float cz, sz; sincosf(0.5f*t3, &sz, &cz);
            float2 ez0 = {cz,-sz}, ez1 = {cz,sz};
            float2 m00 = cmul(ez0,a00), m01 = cmul(ez0,a01);
            float2 m10 = cmul(ez1,a10), m11 = cmul(ez1,a11);
            const int mask = 1 << (NQ - 1 - q);
            for (int p = t; p < DIM/2; p += 256) {
                int i0 = ((p & ~(mask-1)) << 1) | (p & (mask-1));
                int i1 = i0 | mask;
                float2 v0 = st[i0], v1 = st[i1];
                st[i0] = cadd(cmul(m00,v0), cmul(m01,v1));
                st[i1] = cadd(cmul(m10,v0), cmul(m11,v1));
            }
            __syncthreads();
        }
        for (int i = t; i < DIM; i += 256) {
            float ang = 0.f;
            #pragma unroll
            for (int g = 0; g < NQ-1; g++) {
                int b1 = (i >> (NQ-1-g)) & 1;
                int b2 = (i >> (NQ-2-g)) & 1;
                if (b1 & b2) ang += ent[l*(NQ-1) + g];
            }
            float sn, cs; sincosf(ang, &sn, &cs);
            st[i] = cmul(st[i], make_float2(cs, sn));
        }
        __syncthreads();
    }
    if (m < D_MODEL) {
        for (int i = t; i < DIM; i += 256) {
            Cs[(size_t)(2*i)   * D_MODEL + m] = __float2half(st[i].x);
            Cs[(size_t)(2*i+1) * D_MODEL + m] = __float2half(st[i].y);
        }
    } else {
        for (int i = t; i < DIM; i += 256) {
            d[2*i]   = st[i].x;
            d[2*i+1] = st[i].y;
        }
    }
}

// ---------------- conv kernels -----------------------------------------------
__global__ void conv_x(const float* __restrict__ x, __half* __restrict__ xs) {
    int i = blockIdx.x * blockDim.x + threadIdx.x;
    int n = N_TOKENS * D_MODEL / 4;
    if (i >= n) return;
    float4 v = ((const float4*)x)[i];
    __half2 a; a.x = __float2half(v.x); a.y = __float2half(v.y);
    __half2 b; b.x = __float2half(v.z); b.y = __float2half(v.w);
    ((__half2*)xs)[2*i] = a;
    ((__half2*)xs)[2*i + 1] = b;
}

__global__ void conv_Wout(const float* __restrict__ W, __half* __restrict__ Ws) {
    int i = blockIdx.x * blockDim.x + threadIdx.x;
    int n = D_MODEL * DIM / 4;
    if (i >= n) return;
    float4 v = ((const float4*)W)[i];
    __half2 a; a.x = __float2half(v.x); a.y = __float2half(v.y);
    __half2 b; b.x = __float2half(v.z); b.y = __float2half(v.w);
    ((__half2*)Ws)[2*i] = a;
    ((__half2*)Ws)[2*i + 1] = b;
}

// ---------------- reductions / finalize ----------------------------------------
__device__ float blockReduceSum256(float v) {
    __shared__ float sh[8];
    __syncthreads();
    int lane = threadIdx.x & 31, wid = threadIdx.x >> 5;
    #pragma unroll
    for (int o = 16; o > 0; o >>= 1) v += __shfl_down_sync(0xffffffffu, v, o);
    if (lane == 0) sh[wid] = v;
    __syncthreads();
    float s = 0.f;
    if (threadIdx.x < 8) s = sh[threadIdx.x];
    if (wid == 0) {
        #pragma unroll
        for (int o = 4; o > 0; o >>= 1) s += __shfl_down_sync(0xffu, s, o);
        if (lane == 0) sh[0] = s;
    }
    __syncthreads();
    return sh[0];
}

// pre = preU/s + b_out, then LayerNorm -> out
__global__ void finalize(const float* __restrict__ preU,
                         const float* __restrict__ Spart,
                         const float* __restrict__ b_out,
                         const float* __restrict__ w, const float* __restrict__ b,
                         float* __restrict__ out) {
    const int row = blockIdx.x;
    const int t = threadIdx.x;
    float s = 0.f;
    #pragma unroll
    for (int c = 0; c < NXPART; c++) s += Spart[(size_t)c * N_TOKENS + row];
    float inv_s = 1.f / fmaxf(s, 1e-24f);
    const float* p = preU + (size_t)row * D_MODEL;
    float v0 = p[t] * inv_s + b_out[t];
    float v1 = p[t+256] * inv_s + b_out[t+256];
    float mu = blockReduceSum256(v0 + v1) * (1.f / D_MODEL);
    float d0 = v0 - mu, d1 = v1 - mu;
    float var = blockReduceSum256(d0*d0 + d1*d1) * (1.f / D_MODEL);
    float inv = rsqrtf(var + 1e-5f);
    float* o = out + (size_t)row * D_MODEL;
    o[t]     = d0 * inv * w[t]     + b[t];
    o[t+256] = d1 * inv * w[t+256] + b[t+256];
}

// ---------------- launch ---------------------------------------------------------
extern "C" void kernel_launch(void* const* d_in, const int* in_sizes, int n_in,
                              void* d_out, int out_size) {
    const float* x     = (const float*)d_in[0];
    const float* W_in  = (const float*)d_in[1];
    const float* b_in  = (const float*)d_in[2];
    const float* W_out = (const float*)d_in[3];
    const float* b_out = (const float*)d_in[4];
    const float* rot   = (const float*)d_in[5];
    const float* ent   = (const float*)d_in[6];
    const float* ln_w  = (const float*)d_in[7];
    const float* ln_b  = (const float*)d_in[8];
    float* out = (float*)d_out;

    float *dv, *Sp, *pre;
    __half *Cs, *xs, *Q, *Wouts;
    cudaGetSymbolAddress((void**)&Cs,    g_Cs);
    cudaGetSymbolAddress((void**)&dv,    g_d);
    cudaGetSymbolAddress((void**)&xs,    g_xs);
    cudaGetSymbolAddress((void**)&Q,     g_Q);
    cudaGetSymbolAddress((void**)&Sp,    g_S);
    cudaGetSymbolAddress((void**)&Wouts, g_Wouts);
    cudaGetSymbolAddress((void**)&pre,   g_pre);

    cudaFuncSetAttribute(gemm_mma<0>, cudaFuncAttributeMaxDynamicSharedMemorySize, SMEM_TOTAL);
    cudaFuncSetAttribute(gemm_mma<1>, cudaFuncAttributeMaxDynamicSharedMemorySize, SMEM_TOTAL);

    // 1) C = circuit(Win columns), d = circuit(b_in) — direct simulation
    sim_cols<<<D_MODEL + 1, 256>>>(rot, ent, W_in, b_in, Cs, dv);

    // 2) xs = fp16(x); Wouts = fp16(W_out)
    conv_x<<<(N_TOKENS*D_MODEL/4 + 255)/256, 256>>>(x, xs);
    conv_Wout<<<(D_MODEL*DIM/4 + 255)/256, 256>>>(W_out, Wouts);

    // 3) amp GEMM + fused |amp|^2 epilogue: Q fp16 [16384,1024] + row partials
    gemm_mma<1><<<dim3(2048/BN, N_TOKENS/BM), NTHREADS, SMEM_TOTAL>>>(
        xs, Cs, nullptr, Q, Sp, dv, N_TOKENS, 2048, D_MODEL, D_MODEL);

    // 4) preU = Q @ fp16(W_out)^T (unnormalized, no bias)
    gemm_mma<0><<<dim3(D_MODEL/BN, N_TOKENS/BM), NTHREADS, SMEM_TOTAL>>>(
        Q, Wouts, pre, nullptr, nullptr, nullptr, N_TOKENS, D_MODEL, DIM, DIM);

    // 5) finalize: pre/s + b_out, LayerNorm
    finalize<<<N_TOKENS, 256>>>(pre, Sp, b_out, ln_w, ln_b, out);
}

// round 16
// speedup vs baseline: 1.2586x; 1.0019x over previous
#include <cuda_runtime.h>
#include <cuda_fp16.h>
#include <math.h>
#include <stdint.h>

#define N_TOKENS 16384
#define D_MODEL  512
#define NQ       10
#define NL       2
#define DIM      1024

#define BM 128
#define BN 128
#define BKB 128                    // K bytes per stage (64 fp16)
#define NSTAGES 3
#define TILE_A (BM*BKB)            // 16 KB
#define TILE_Bb (BN*BKB)           // 16 KB
#define STAGE_B (TILE_A+TILE_Bb)   // 32 KB
#define SMEM_TOTAL (NSTAGES*STAGE_B)   // 96 KB -> 2 CTAs/SM
#define NTHREADS 128               // 4 warps, 2x2 grid of 64x64 warp tiles
#define NXPART 16                  // amp GEMM column tiles (2048/BN)

__device__ __align__(16) __half g_Cs[2048*D_MODEL];     // fp16(C) [2048,512]
__device__ __align__(16) float  g_d[2048];              // circuit(b_in)
__device__ __align__(16) __half g_xs[N_TOKENS*D_MODEL]; // fp16(x)
__device__ __align__(16) __half g_Q[N_TOKENS*DIM];      // fp16(|amp|^2) unnorm
__device__ __align__(16) float  g_S[NXPART*N_TOKENS];   // per-row partial sums
__device__ __align__(16) __half g_Wouts[D_MODEL*DIM];   // fp16(W_out)
__device__ __align__(16) float  g_pre[2*N_TOKENS*D_MODEL]; // split-K partials

// ---------------- PTX helpers (sm_80-era only; no 'a' features) --------------
__device__ __forceinline__ uint32_t smem_u32(const void* p) {
    return (uint32_t)__cvta_generic_to_shared(p);
}
#define CP16(saddr, gaddr) \
    asm volatile("cp.async.cg.shared.global [%0], [%1], 16;" \
                 :: "r"(saddr), "l"(gaddr) : "memory")
#define CP_COMMIT() asm volatile("cp.async.commit_group;" ::: "memory")
#define CP_WAIT1()  asm volatile("cp.async.wait_group 1;" ::: "memory")

#define LDSM4(r0,r1,r2,r3,addr) \
    asm volatile("ldmatrix.sync.aligned.m8n8.x4.shared.b16 {%0,%1,%2,%3}, [%4];" \
                 : "=r"(r0), "=r"(r1), "=r"(r2), "=r"(r3) : "r"(addr))

#define MMA16816(c, a0,a1,a2,a3, b0,b1) \
    asm volatile("mma.sync.aligned.m16n8k16.row.col.f32.f16.f16.f32 " \
                 "{%0,%1,%2,%3}, {%4,%5,%6,%7}, {%8,%9}, {%0,%1,%2,%3};" \
                 : "+f"((c)[0]), "+f"((c)[1]), "+f"((c)[2]), "+f"((c)[3]) \
                 : "r"(a0), "r"(a1), "r"(a2), "r"(a3), "r"(b0), "r"(b1))

#define SW128(off) ((off) ^ (((off) >> 3) & 0x70))

// ---- fp16 mma GEMM (128x128 tile, 64x64 warp tile, 128 thr, 2 CTAs/SM) ------
// (LOCKED engine; split-K via blockIdx.z: reads A,B at K-offset z*Ks, writes
//  partial to C + z*M*N.)
// EPI=0: C[M,N] = A @ B^T (fp32 partial)
// EPI=1: cols are (re,im) pairs; q = (re+d)^2+(im+d')^2 -> Q fp16 [M, N/2];
//        deterministic per-row partial sums -> Spart[blockIdx.x*M + row].
template<int EPI>
__global__ __launch_bounds__(NTHREADS, 2)
void gemm_mma(const __half* __restrict__ A,
              const __half* __restrict__ B,
              float* __restrict__ C,
              __half* __restrict__ Q,
              float* __restrict__ Spart,
              const float* __restrict__ bias,
              int M, int N, int Ks, int Kfull)
{
    extern __shared__ char smem[];
    __shared__ float s_w[2][BM];
    const uint32_t S0 = smem_u32(smem);
    const int tid  = threadIdx.x;
    const int wid  = tid >> 5;
    const int lane = tid & 31;
    const int warp_m = (wid & 1) * 64;
    const int warp_n = (wid >> 1) * 64;
    const int m0 = blockIdx.y * BM;
    const int n0 = blockIdx.x * BN;
    const int nks = Ks / 64;

    const size_t ldb = (size_t)Kfull * 2;
    const size_t koff = (size_t)blockIdx.z * Ks * 2;
    const size_t Ab = (size_t)__cvta_generic_to_global(A) + (size_t)m0 * ldb + koff;
    const size_t Bb = (size_t)__cvta_generic_to_global(B) + (size_t)n0 * ldb + koff;

    const int a_row = (lane & 15);
    const int a_koff = (lane >> 4) << 4;
    const int b_row = (lane & 7) + ((lane >> 4) << 3);
    const int b_koff = ((lane >> 3) & 1) << 4;

    float c[4][8][4];
    #pragma unroll
    for (int mt = 0; mt < 4; mt++)
        #pragma unroll
        for (int nt = 0; nt < 8; nt++)
            #pragma unroll
            for (int j = 0; j < 4; j++) c[mt][nt][j] = 0.f;

    #pragma unroll
    for (int s = 0; s < NSTAGES - 1; s++) {
        const uint32_t saA = S0 + s * STAGE_B;
        const uint32_t saB = saA + TILE_A;
        const size_t ka = Ab + (size_t)s * BKB;
        const size_t kb = Bb + (size_t)s * BKB;
        #pragma unroll
        for (int i = 0; i < 16; i++) {
            int cc = tid + NTHREADS * i;
            if (cc < 1024) {
                int r = cc >> 3, p = (cc & 7) * 16;
                CP16(saA + SW128(r*128 + p), ka + (size_t)r * ldb + p);
            } else {
                int c2 = cc - 1024;
                int r = c2 >> 3, p = (c2 & 7) * 16;
                CP16(saB + SW128(r*128 + p), kb + (size_t)r * ldb + p);
            }
        }
        CP_COMMIT();
    }

    for (int ks = 0; ks < nks; ks++) {
        CP_WAIT1();
        __syncthreads();

        int ld = ks + NSTAGES - 1;
        if (ld < nks) {
            int slot = ld % NSTAGES;
            const uint32_t pA = S0 + slot * STAGE_B;
            const uint32_t pB = pA + TILE_A;
            const size_t ka = Ab + (size_t)ld * BKB;
            const size_t kb = Bb + (size_t)ld * BKB;
            #pragma unroll
            for (int i = 0; i < 16; i++) {
                int cc = tid + NTHREADS * i;
                if (cc < 1024) {
                    int r = cc >> 3, p = (cc & 7) * 16;
                    CP16(pA + SW128(r*128 + p), ka + (size_t)r * ldb + p);
                } else {
                    int c2 = cc - 1024;
                    int r = c2 >> 3, p = (c2 & 7) * 16;
                    CP16(pB + SW128(r*128 + p), kb + (size_t)r * ldb + p);
                }
            }
        }
        CP_COMMIT();

        const uint32_t saA = S0 + (ks % NSTAGES) * STAGE_B;
        const uint32_t saB = saA + TILE_A;
        #pragma unroll
        for (int kk = 0; kk < 4; kk++) {
            uint32_t a[4][4], b[4][4];
            #pragma unroll
            for (int mt = 0; mt < 4; mt++) {
                int r = warp_m + mt*16 + a_row;
                LDSM4(a[mt][0], a[mt][1], a[mt][2], a[mt][3],
                      saA + SW128(r*128 + kk*32 + a_koff));
            }
            #pragma unroll
            for (int nt2 = 0; nt2 < 4; nt2++) {
                int r = warp_n + nt2*16 + b_row;
                LDSM4(b[nt2][0], b[nt2][1], b[nt2][2], b[nt2][3],
                      saB + SW128(r*128 + kk*32 + b_koff));
            }
            #pragma unroll
            for (int mt = 0; mt < 4; mt++)
                #pragma unroll
                for (int nt = 0; nt < 8; nt++)
                    MMA16816(c[mt][nt],
                             a[mt][0], a[mt][1], a[mt][2], a[mt][3],
                             b[nt >> 1][(nt & 1) * 2],
                             b[nt >> 1][(nt & 1) * 2 + 1]);
        }
    }

    if (EPI == 0) {
        float* Cz = C + (size_t)blockIdx.z * M * N;
        #pragma unroll
        for (int mt = 0; mt < 4; mt++) {
            int r0 = m0 + warp_m + mt*16 + (lane >> 2);
            #pragma unroll
            for (int nt = 0; nt < 8; nt++) {
                int nn = n0 + warp_n + nt*8 + 2*(lane & 3);
                float2 v0 = make_float2(c[mt][nt][0], c[mt][nt][1]);
                float2 v1 = make_float2(c[mt][nt][2], c[mt][nt][3]);
                *(float2*)(Cz + (size_t)r0 * N + nn) = v0;
                *(float2*)(Cz + (size_t)(r0+8) * N + nn) = v1;
            }
        }
    } else {
        const int Nq = N >> 1;
        #pragma unroll
        for (int mt = 0; mt < 4; mt++) {
            int rl0 = warp_m + mt*16 + (lane >> 2);
            float sum0 = 0.f, sum1 = 0.f;
            #pragma unroll
            for (int nt = 0; nt < 8; nt++) {
                int nn = n0 + warp_n + nt*8 + 2*(lane & 3);
                float dr = bias[nn], di = bias[nn+1];
                float re0 = c[mt][nt][0] + dr, im0 = c[mt][nt][1] + di;
                float re1 = c[mt][nt][2] + dr, im1 = c[mt][nt][3] + di;
                float q0 = re0*re0 + im0*im0;
                float q1 = re1*re1 + im1*im1;
                int pcol = (nn >> 1);
                Q[(size_t)(m0 + rl0) * Nq + pcol]     = __float2half(q0);
                Q[(size_t)(m0 + rl0 + 8) * Nq + pcol] = __float2half(q1);
                sum0 += q0; sum1 += q1;
            }
            sum0 += __shfl_down_sync(0xffffffffu, sum0, 2);
            sum0 += __shfl_down_sync(0xffffffffu, sum0, 1);
            sum1 += __shfl_down_sync(0xffffffffu, sum1, 2);
            sum1 += __shfl_down_sync(0xffffffffu, sum1, 1);
            if ((lane & 3) == 0) {
                s_w[wid >> 1][rl0]     = sum0;
                s_w[wid >> 1][rl0 + 8] = sum1;
            }
        }
        __syncthreads();
        if (tid < BM) {
            Spart[(size_t)blockIdx.x * M + m0 + tid] = s_w[0][tid] + s_w[1][tid];
        }
    }
}

// ---- circuit sim applied directly to Win columns (and b_in) -----------------
__device__ __forceinline__ float2 cmul(float2 a, float2 b) {
    return make_float2(a.x*b.x - a.y*b.y, a.x*b.y + a.y*b.x);
}
__device__ __forceinline__ float2 cadd(float2 a, float2 b) {
    return make_float2(a.x + b.x, a.y + b.y);
}

__global__ void sim_cols(const float* __restrict__ rot,
                         const float* __restrict__ ent,
                         const float* __restrict__ W_in,
                         const float* __restrict__ b_in,
                         __half* __restrict__ Cs, float* __restrict__ d) {
    __shared__ float2 st[DIM];
    const int m = blockIdx.x;   // 0..512
    const int t = threadIdx.x;  // 256 threads
    for (int i = t; i < DIM; i += 256) {
        float v = (m < D_MODEL) ? W_in[(size_t)i * D_MODEL + m] : b_in[i];
        st[i] = make_float2(v, 0.f);
    }
    __syncthreads();
    for (int l = 0; l < NL; l++) {
        for (int q = 0; q < NQ; q++) {
            const float t1 = rot[(l*NQ + q)*3 + 0];
            const float t2 = rot[(l*NQ + q)*3 + 1];
            const float t3 = rot[(l*NQ + q)*3 + 2];
            float c1, s1; sincosf(0.5f*t1, &s1, &c1);
            float2 rx00 = {c1,0.f}, rx01 = {0.f,-s1}, rx10 = {0.f,-s1}, rx11 = {c1,0.f};
            float c2, s2; sincosf(0.5f*t2, &s2, &c2);
            float2 ry00 = {c2,0.f}, ry01 = {-s2,0.f}, ry10 = {s2,0.f}, ry11 = {c2,0.f};
            float2 a00 = cadd(cmul(ry00,rx00), cmul(ry01,rx10));
            float2 a01 = cadd(cmul(ry00,rx01), cmul(ry01,rx11));
            float2 a10 = cadd(cmul(ry10,rx00), cmul(ry11,rx10));
            float2 a11 = cadd(cmul(ry10,rx01), cmul(ry11,rx11));
            float cz, sz; sincosf(0.5f*t3, &sz, &cz);
            float2 ez0 = {cz,-sz}, ez1 = {cz,sz};
            float2 m00 = cmul(ez0,a00), m01 = cmul(ez0,a01);
            float2 m10 = cmul(ez1,a10), m11 = cmul(ez1,a11);
            const int mask = 1 << (NQ - 1 - q);
            for (int p = t; p < DIM/2; p += 256) {
                int i0 = ((p & ~(mask-1)) << 1) | (p & (mask-1));
                int i1 = i0 | mask;
                float2 v0 = st[i0], v1 = st[i1];
                st[i0] = cadd(cmul(m00,v0), cmul(m01,v1));
                st[i1] = cadd(cmul(m10,v0), cmul(m11,v1));
            }
            __syncthreads();
        }
        for (int i = t; i < DIM; i += 256) {
            float ang = 0.f;
            #pragma unroll
            for (int g = 0; g < NQ-1; g++) {
                int b1 = (i >> (NQ-1-g)) & 1;
                int b2 = (i >> (NQ-2-g)) & 1;
                if (b1 & b2) ang += ent[l*(NQ-1) + g];
            }
            float sn, cs; sincosf(ang, &sn, &cs);
            st[i] = cmul(st[i], make_float2(cs, sn));
        }
        __syncthreads();
    }
    if (m < D_MODEL) {
        for (int i = t; i < DIM; i += 256) {
            Cs[(size_t)(2*i)   * D_MODEL + m] = __float2half(st[i].x);
            Cs[(size_t)(2*i+1) * D_MODEL + m] = __float2half(st[i].y);
        }
    } else {
        for (int i = t; i < DIM; i += 256) {
            d[2*i]   = st[i].x;
            d[2*i+1] = st[i].y;
        }
    }
}

// ---------------- fused fp32->fp16 conversions (x then W_out) ----------------
__global__ void conv_all(const float* __restrict__ x, __half* __restrict__ xs,
                         const float* __restrict__ W, __half* __restrict__ Ws) {
    const int nx = N_TOKENS * D_MODEL / 4;
    const int nw = D_MODEL * DIM / 4;
    int i = blockIdx.x * blockDim.x + threadIdx.x;
    if (i < nx) {
        float4 v = ((const float4*)x)[i];
        __half2 a; a.x = __float2half(v.x); a.y = __float2half(v.y);
        __half2 b; b.x = __float2half(v.z); b.y = __float2half(v.w);
        ((__half2*)xs)[2*i] = a;
        ((__half2*)xs)[2*i + 1] = b;
    } else if (i < nx + nw) {
        int k = i - nx;
        float4 v = ((const float4*)W)[k];
        __half2 a; a.x = __float2half(v.x); a.y = __float2half(v.y);
        __half2 b; b.x = __float2half(v.z); b.y = __float2half(v.w);
        ((__half2*)Ws)[2*k] = a;
        ((__half2*)Ws)[2*k + 1] = b;
    }
}

// ---------------- reductions / finalize ----------------------------------------
__device__ float blockReduceSum256(float v) {
    __shared__ float sh[8];
    __syncthreads();
    int lane = threadIdx.x & 31, wid = threadIdx.x >> 5;
    #pragma unroll
    for (int o = 16; o > 0; o >>= 1) v += __shfl_down_sync(0xffffffffu, v, o);
    if (lane == 0) sh[wid] = v;
    __syncthreads();
    float s = 0.f;
    if (threadIdx.x < 8) s = sh[threadIdx.x];
    if (wid == 0) {
        #pragma unroll
        for (int o = 4; o > 0; o >>= 1) s += __shfl_down_sync(0xffu, s, o);
        if (lane == 0) sh[0] = s;
    }
    __syncthreads();
    return sh[0];
}

// pre = (preU0+preU1)/s + b_out, then LayerNorm -> out
__global__ void finalize(const float* __restrict__ preU,
                         const float* __restrict__ Spart,
                         const float* __restrict__ b_out,
                         const float* __restrict__ w, const float* __restrict__ b,
                         float* __restrict__ out) {
    const int row = blockIdx.x;
    const int t = threadIdx.x;
    float s = 0.f;
    #pragma unroll
    for (int c = 0; c < NXPART; c++) s += Spart[(size_t)c * N_TOKENS + row];
    float inv_s = 1.f / fmaxf(s, 1e-24f);
    const float* p0 = preU + (size_t)row * D_MODEL;
    const float* p1 = preU + (size_t)N_TOKENS * D_MODEL + (size_t)row * D_MODEL;
    float v0 = (p0[t]     + p1[t])     * inv_s + b_out[t];
    float v1 = (p0[t+256] + p1[t+256]) * inv_s + b_out[t+256];
    float mu = blockReduceSum256(v0 + v1) * (1.f / D_MODEL);
    float d0 = v0 - mu, d1 = v1 - mu;
    float var = blockReduceSum256(d0*d0 + d1*d1) * (1.f / D_MODEL);
    float inv = rsqrtf(var + 1e-5f);
    float* o = out + (size_t)row * D_MODEL;
    o[t]     = d0 * inv * w[t]     + b[t];
    o[t+256] = d1 * inv * w[t+256] + b[t+256];
}

// ---------------- launch ---------------------------------------------------------
extern "C" void kernel_launch(void* const* d_in, const int* in_sizes, int n_in,
                              void* d_out, int out_size) {
    const float* x     = (const float*)d_in[0];
    const float* W_in  = (const float*)d_in[1];
    const float* b_in  = (const float*)d_in[2];
    const float* W_out = (const float*)d_in[3];
    const float* b_out = (const float*)d_in[4];
    const float* rot   = (const float*)d_in[5];
    const float* ent   = (const float*)d_in[6];
    const float* ln_w  = (const float*)d_in[7];
    const float* ln_b  = (const float*)d_in[8];
    float* out = (float*)d_out;

    float *dv, *Sp, *pre;
    __half *Cs, *xs, *Q, *Wouts;
    cudaGetSymbolAddress((void**)&Cs,    g_Cs);
    cudaGetSymbolAddress((void**)&dv,    g_d);
    cudaGetSymbolAddress((void**)&xs,    g_xs);
    cudaGetSymbolAddress((void**)&Q,     g_Q);
    cudaGetSymbolAddress((void**)&Sp,    g_S);
    cudaGetSymbolAddress((void**)&Wouts, g_Wouts);
    cudaGetSymbolAddress((void**)&pre,   g_pre);

    cudaFuncSetAttribute(gemm_mma<0>, cudaFuncAttributeMaxDynamicSharedMemorySize, SMEM_TOTAL);
    cudaFuncSetAttribute(gemm_mma<1>, cudaFuncAttributeMaxDynamicSharedMemorySize, SMEM_TOTAL);

    // 1) C = circuit(Win columns), d = circuit(b_in) — direct simulation
    sim_cols<<<D_MODEL + 1, 256>>>(rot, ent, W_in, b_in, Cs, dv);

    // 2) xs = fp16(x); Wouts = fp16(W_out) — single fused launch
    const int nconv = (N_TOKENS*D_MODEL + D_MODEL*DIM) / 4;
    conv_all<<<(nconv + 255)/256, 256>>>(x, xs, W_out, Wouts);

    // 3) amp GEMM + fused |amp|^2 epilogue: Q fp16 [16384,1024] + row partials
    gemm_mma<1><<<dim3(2048/BN, N_TOKENS/BM, 1), NTHREADS, SMEM_TOTAL>>>(
        xs, Cs, nullptr, Q, Sp, dv, N_TOKENS, 2048, D_MODEL, D_MODEL);

    // 4) preU(z) = Q @ fp16(W_out)^T — split-K z=2 for wave-quantization
    gemm_mma<0><<<dim3(D_MODEL/BN, N_TOKENS/BM, 2), NTHREADS, SMEM_TOTAL>>>(
        Q, Wouts, pre, nullptr, nullptr, nullptr, N_TOKENS, D_MODEL, DIM/2, DIM);

    // 5) finalize: (preU0+preU1)/s + b_out, LayerNorm
    finalize<<<N_TOKENS, 256>>>(pre, Sp, b_out, ln_w, ln_b, out);
}

// round 17
// speedup vs baseline: 1.3186x; 1.0477x over previous
#include <cuda_runtime.h>
#include <cuda_fp16.h>
#include <math.h>
#include <stdint.h>

#define N_TOKENS 16384
#define D_MODEL  512
#define NQ       10
#define NL       2
#define DIM      1024

#define BM 128
#define BN 128
#define BKB 128                    // K bytes per stage (64 fp16)
#define NSTAGES 3
#define TILE_A (BM*BKB)            // 16 KB
#define TILE_Bb (BN*BKB)           // 16 KB
#define STAGE_B (TILE_A+TILE_Bb)   // 32 KB
#define SMEM_TOTAL (NSTAGES*STAGE_B)   // 96 KB -> 2 CTAs/SM
#define NTHREADS 128               // 4 warps, 2x2 grid of 64x64 warp tiles
#define NXPART 16                  // amp GEMM column tiles (2048/BN)

#define NSIMB (D_MODEL + 1)        // 513 sim blocks
#define NCONV ((N_TOKENS*D_MODEL + D_MODEL*DIM) / 4)   // float4 chunks
#define NCONVB ((NCONV + 255) / 256)

__device__ __align__(16) __half g_Cs[2048*D_MODEL];     // fp16(C) [2048,512]
__device__ __align__(16) float  g_d[2048];              // circuit(b_in)
__device__ __align__(16) __half g_xs[N_TOKENS*D_MODEL]; // fp16(x)
__device__ __align__(16) __half g_Q[N_TOKENS*DIM];      // fp16(|amp|^2) unnorm
__device__ __align__(16) float  g_S[NXPART*N_TOKENS];   // per-row partial sums
__device__ __align__(16) __half g_Wouts[D_MODEL*DIM];   // fp16(W_out)
__device__ __align__(16) float  g_pre[N_TOKENS*D_MODEL];

// ---------------- PTX helpers (sm_80-era only; no 'a' features) --------------
__device__ __forceinline__ uint32_t smem_u32(const void* p) {
    return (uint32_t)__cvta_generic_to_shared(p);
}
#define CP16(saddr, gaddr) \
    asm volatile("cp.async.cg.shared.global [%0], [%1], 16;" \
                 :: "r"(saddr), "l"(gaddr) : "memory")
#define CP_COMMIT() asm volatile("cp.async.commit_group;" ::: "memory")
#define CP_WAIT1()  asm volatile("cp.async.wait_group 1;" ::: "memory")

#define LDSM4(r0,r1,r2,r3,addr) \
    asm volatile("ldmatrix.sync.aligned.m8n8.x4.shared.b16 {%0,%1,%2,%3}, [%4];" \
                 : "=r"(r0), "=r"(r1), "=r"(r2), "=r"(r3) : "r"(addr))

#define MMA16816(c, a0,a1,a2,a3, b0,b1) \
    asm volatile("mma.sync.aligned.m16n8k16.row.col.f32.f16.f16.f32 " \
                 "{%0,%1,%2,%3}, {%4,%5,%6,%7}, {%8,%9}, {%0,%1,%2,%3};" \
                 : "+f"((c)[0]), "+f"((c)[1]), "+f"((c)[2]), "+f"((c)[3]) \
                 : "r"(a0), "r"(a1), "r"(a2), "r"(a3), "r"(b0), "r"(b1))

#define SW128(off) ((off) ^ (((off) >> 3) & 0x70))

// ---- fp16 mma GEMM (128x128 tile, 64x64 warp tile, 128 thr, 2 CTAs/SM) ------
// (LOCKED engine)
// EPI=0: C[M,N] = A @ B^T (fp32)
// EPI=1: cols are (re,im) pairs; q = (re+d)^2+(im+d')^2 -> Q fp16 [M, N/2];
//        deterministic per-row partial sums -> Spart[blockIdx.x*M + row].
template<int EPI>
__global__ __launch_bounds__(NTHREADS, 2)
void gemm_mma(const __half* __restrict__ A,
              const __half* __restrict__ B,
              float* __restrict__ C,
              __half* __restrict__ Q,
              float* __restrict__ Spart,
              const float* __restrict__ bias,
              int M, int N, int Ks, int Kfull)
{
    extern __shared__ char smem[];
    __shared__ float s_w[2][BM];
    const uint32_t S0 = smem_u32(smem);
    const int tid  = threadIdx.x;
    const int wid  = tid >> 5;
    const int lane = tid & 31;
    const int warp_m = (wid & 1) * 64;
    const int warp_n = (wid >> 1) * 64;
    const int m0 = blockIdx.y * BM;
    const int n0 = blockIdx.x * BN;
    const int nks = Ks / 64;

    const size_t ldb = (size_t)Kfull * 2;
    const size_t Ab = (size_t)__cvta_generic_to_global(A) + (size_t)m0 * ldb;
    const size_t Bb = (size_t)__cvta_generic_to_global(B) + (size_t)n0 * ldb;

    const int a_row = (lane & 15);
    const int a_koff = (lane >> 4) << 4;
    const int b_row = (lane & 7) + ((lane >> 4) << 3);
    const int b_koff = ((lane >> 3) & 1) << 4;

    float c[4][8][4];
    #pragma unroll
    for (int mt = 0; mt < 4; mt++)
        #pragma unroll
        for (int nt = 0; nt < 8; nt++)
            #pragma unroll
            for (int j = 0; j < 4; j++) c[mt][nt][j] = 0.f;

    #pragma unroll
    for (int s = 0; s < NSTAGES - 1; s++) {
        const uint32_t saA = S0 + s * STAGE_B;
        const uint32_t saB = saA + TILE_A;
        const size_t ka = Ab + (size_t)s * BKB;
        const size_t kb = Bb + (size_t)s * BKB;
        #pragma unroll
        for (int i = 0; i < 16; i++) {
            int cc = tid + NTHREADS * i;
            if (cc < 1024) {
                int r = cc >> 3, p = (cc & 7) * 16;
                CP16(saA + SW128(r*128 + p), ka + (size_t)r * ldb + p);
            } else {
                int c2 = cc - 1024;
                int r = c2 >> 3, p = (c2 & 7) * 16;
                CP16(saB + SW128(r*128 + p), kb + (size_t)r * ldb + p);
            }
        }
        CP_COMMIT();
    }

    for (int ks = 0; ks < nks; ks++) {
        CP_WAIT1();
        __syncthreads();

        int ld = ks + NSTAGES - 1;
        if (ld < nks) {
            int slot = ld % NSTAGES;
            const uint32_t pA = S0 + slot * STAGE_B;
            const uint32_t pB = pA + TILE_A;
            const size_t ka = Ab + (size_t)ld * BKB;
            const size_t kb = Bb + (size_t)ld * BKB;
            #pragma unroll
            for (int i = 0; i < 16; i++) {
                int cc = tid + NTHREADS * i;
                if (cc < 1024) {
                    int r = cc >> 3, p = (cc & 7) * 16;
                    CP16(pA + SW128(r*128 + p), ka + (size_t)r * ldb + p);
                } else {
                    int c2 = cc - 1024;
                    int r = c2 >> 3, p = (c2 & 7) * 16;
                    CP16(pB + SW128(r*128 + p), kb + (size_t)r * ldb + p);
                }
            }
        }
        CP_COMMIT();

        const uint32_t saA = S0 + (ks % NSTAGES) * STAGE_B;
        const uint32_t saB = saA + TILE_A;
        #pragma unroll
        for (int kk = 0; kk < 4; kk++) {
            uint32_t a[4][4], b[4][4];
            #pragma unroll
            for (int mt = 0; mt < 4; mt++) {
                int r = warp_m + mt*16 + a_row;
                LDSM4(a[mt][0], a[mt][1], a[mt][2], a[mt][3],
                      saA + SW128(r*128 + kk*32 + a_koff));
            }
            #pragma unroll
            for (int nt2 = 0; nt2 < 4; nt2++) {
                int r = warp_n + nt2*16 + b_row;
                LDSM4(b[nt2][0], b[nt2][1], b[nt2][2], b[nt2][3],
                      saB + SW128(r*128 + kk*32 + b_koff));
            }
            #pragma unroll
            for (int mt = 0; mt < 4; mt++)
                #pragma unroll
                for (int nt = 0; nt < 8; nt++)
                    MMA16816(c[mt][nt],
                             a[mt][0], a[mt][1], a[mt][2], a[mt][3],
                             b[nt >> 1][(nt & 1) * 2],
                             b[nt >> 1][(nt & 1) * 2 + 1]);
        }
    }

    if (EPI == 0) {
        #pragma unroll
        for (int mt = 0; mt < 4; mt++) {
            int r0 = m0 + warp_m + mt*16 + (lane >> 2);
            #pragma unroll
            for (int nt = 0; nt < 8; nt++) {
                int nn = n0 + warp_n + nt*8 + 2*(lane & 3);
                float2 v0 = make_float2(c[mt][nt][0], c[mt][nt][1]);
                float2 v1 = make_float2(c[mt][nt][2], c[mt][nt][3]);
                *(float2*)(C + (size_t)r0 * N + nn) = v0;
                *(float2*)(C + (size_t)(r0+8) * N + nn) = v1;
            }
        }
    } else {
        const int Nq = N >> 1;
        #pragma unroll
        for (int mt = 0; mt < 4; mt++) {
            int rl0 = warp_m + mt*16 + (lane >> 2);
            float sum0 = 0.f, sum1 = 0.f;
            #pragma unroll
            for (int nt = 0; nt < 8; nt++) {
                int nn = n0 + warp_n + nt*8 + 2*(lane & 3);
                float dr = bias[nn], di = bias[nn+1];
                float re0 = c[mt][nt][0] + dr, im0 = c[mt][nt][1] + di;
                float re1 = c[mt][nt][2] + dr, im1 = c[mt][nt][3] + di;
                float q0 = re0*re0 + im0*im0;
                float q1 = re1*re1 + im1*im1;
                int pcol = (nn >> 1);
                Q[(size_t)(m0 + rl0) * Nq + pcol]     = __float2half(q0);
                Q[(size_t)(m0 + rl0 + 8) * Nq + pcol] = __float2half(q1);
                sum0 += q0; sum1 += q1;
            }
            sum0 += __shfl_down_sync(0xffffffffu, sum0, 2);
            sum0 += __shfl_down_sync(0xffffffffu, sum0, 1);
            sum1 += __shfl_down_sync(0xffffffffu, sum1, 2);
            sum1 += __shfl_down_sync(0xffffffffu, sum1, 1);
            if ((lane & 3) == 0) {
                s_w[wid >> 1][rl0]     = sum0;
                s_w[wid >> 1][rl0 + 8] = sum1;
            }
        }
        __syncthreads();
        if (tid < BM) {
            Spart[(size_t)blockIdx.x * M + m0 + tid] = s_w[0][tid] + s_w[1][tid];
        }
    }
}

// ---- fused prep: blocks 0..512 simulate circuit columns; rest convert -------
// sim block m<512: psi0 = Win[:,m] -> Cs[2i][m], Cs[2i+1][m] (fp16)
// sim block m==512: psi0 = b_in -> d (fp32)
// conv blocks: fp16 conversion of x then W_out (float4 chunks)
__device__ __forceinline__ float2 cmul(float2 a, float2 b) {
    return make_float2(a.x*b.x - a.y*b.y, a.x*b.y + a.y*b.x);
}
__device__ __forceinline__ float2 cadd(float2 a, float2 b) {
    return make_float2(a.x + b.x, a.y + b.y);
}

__global__ void prep_all(const float* __restrict__ rot,
                         const float* __restrict__ ent,
                         const float* __restrict__ W_in,
                         const float* __restrict__ b_in,
                         const float* __restrict__ x,
                         const float* __restrict__ W_out,
                         __half* __restrict__ Cs, float* __restrict__ d,
                         __half* __restrict__ xs, __half* __restrict__ Ws) {
    if (blockIdx.x >= NSIMB) {
        // ---- conversion path ----
        const int nx = N_TOKENS * D_MODEL / 4;
        int i = (blockIdx.x - NSIMB) * 256 + threadIdx.x;
        if (i < nx) {
            float4 v = ((const float4*)x)[i];
            __half2 a; a.x = __float2half(v.x); a.y = __float2half(v.y);
            __half2 b; b.x = __float2half(v.z); b.y = __float2half(v.w);
            ((__half2*)xs)[2*i] = a;
            ((__half2*)xs)[2*i + 1] = b;
        } else if (i < NCONV) {
            int k = i - nx;
            float4 v = ((const float4*)W_out)[k];
            __half2 a; a.x = __float2half(v.x); a.y = __float2half(v.y);
            __half2 b; b.x = __float2half(v.z); b.y = __float2half(v.w);
            ((__half2*)Ws)[2*k] = a;
            ((__half2*)Ws)[2*k + 1] = b;
        }
        return;
    }
    // ---- circuit simulation path ----
    __shared__ float2 st[DIM];
    const int m = blockIdx.x;   // 0..512
    const int t = threadIdx.x;  // 256 threads
    for (int i = t; i < DIM; i += 256) {
        float v = (m < D_MODEL) ? W_in[(size_t)i * D_MODEL + m] : b_in[i];
        st[i] = make_float2(v, 0.f);
    }
    __syncthreads();
    for (int l = 0; l < NL; l++) {
        for (int q = 0; q < NQ; q++) {
            const float t1 = rot[(l*NQ + q)*3 + 0];
            const float t2 = rot[(l*NQ + q)*3 + 1];
            const float t3 = rot[(l*NQ + q)*3 + 2];
            float c1, s1; sincosf(0.5f*t1, &s1, &c1);
            float2 rx00 = {c1,0.f}, rx01 = {0.f,-s1}, rx10 = {0.f,-s1}, rx11 = {c1,0.f};
            float c2, s2; sincosf(0.5f*t2, &s2, &c2);
            float2 ry00 = {c2,0.f}, ry01 = {-s2,0.f}, ry10 = {s2,0.f}, ry11 = {c2,0.f};
            float2 a00 = cadd(cmul(ry00,rx00), cmul(ry01,rx10));
            float2 a01 = cadd(cmul(ry00,rx01), cmul(ry01,rx11));
            float2 a10 = cadd(cmul(ry10,rx00), cmul(ry11,rx10));
            float2 a11 = cadd(cmul(ry10,rx01), cmul(ry11,rx11));
            float cz, sz; sincosf(0.5f*t3, &sz, &cz);
            float2 ez0 = {cz,-sz}, ez1 = {cz,sz};
            float2 m00 = cmul(ez0,a00), m01 = cmul(ez0,a01);
            float2 m10 = cmul(ez1,a10), m11 = cmul(ez1,a11);
            const int mask = 1 << (NQ - 1 - q);
            for (int p = t; p < DIM/2; p += 256) {
                int i0 = ((p & ~(mask-1)) << 1) | (p & (mask-1));
                int i1 = i0 | mask;
                float2 v0 = st[i0], v1 = st[i1];
                st[i0] = cadd(cmul(m00,v0), cmul(m01,v1));
                st[i1] = cadd(cmul(m10,v0), cmul(m11,v1));
            }
            __syncthreads();
        }
        for (int i = t; i < DIM; i += 256) {
            float ang = 0.f;
            #pragma unroll
            for (int g = 0; g < NQ-1; g++) {
                int b1 = (i >> (NQ-1-g)) & 1;
                int b2 = (i >> (NQ-2-g)) & 1;
                if (b1 & b2) ang += ent[l*(NQ-1) + g];
            }
            float sn, cs; sincosf(ang, &sn, &cs);
            st[i] = cmul(st[i], make_float2(cs, sn));
        }
        __syncthreads();
    }
    if (m < D_MODEL) {
        for (int i = t; i < DIM; i += 256) {
            Cs[(size_t)(2*i)   * D_MODEL + m] = __float2half(st[i].x);
            Cs[(size_t)(2*i+1) * D_MODEL + m] = __float2half(st[i].y);
        }
    } else {
        for (int i = t; i < DIM; i += 256) {
            d[2*i]   = st[i].x;
            d[2*i+1] = st[i].y;
        }
    }
}

// ---------------- reductions / finalize ----------------------------------------
__device__ float blockReduceSum256(float v) {
    __shared__ float sh[8];
    __syncthreads();
    int lane = threadIdx.x & 31, wid = threadIdx.x >> 5;
    #pragma unroll
    for (int o = 16; o > 0; o >>= 1) v += __shfl_down_sync(0xffffffffu, v, o);
    if (lane == 0) sh[wid] = v;
    __syncthreads();
    float s = 0.f;
    if (threadIdx.x < 8) s = sh[threadIdx.x];
    if (wid == 0) {
        #pragma unroll
        for (int o = 4; o > 0; o >>= 1) s += __shfl_down_sync(0xffu, s, o);
        if (lane == 0) sh[0] = s;
    }
    __syncthreads();
    return sh[0];
}

// pre = preU/s + b_out, then LayerNorm -> out
__global__ void finalize(const float* __restrict__ preU,
                         const float* __restrict__ Spart,
                         const float* __restrict__ b_out,
                         const float* __restrict__ w, const float* __restrict__ b,
                         float* __restrict__ out) {
    const int row = blockIdx.x;
    const int t = threadIdx.x;
    float s = 0.f;
    #pragma unroll
    for (int c = 0; c < NXPART; c++) s += Spart[(size_t)c * N_TOKENS + row];
    float inv_s = 1.f / fmaxf(s, 1e-24f);
    const float* p = preU + (size_t)row * D_MODEL;
    float v0 = p[t] * inv_s + b_out[t];
    float v1 = p[t+256] * inv_s + b_out[t+256];
    float mu = blockReduceSum256(v0 + v1) * (1.f / D_MODEL);
    float d0 = v0 - mu, d1 = v1 - mu;
    float var = blockReduceSum256(d0*d0 + d1*d1) * (1.f / D_MODEL);
    float inv = rsqrtf(var + 1e-5f);
    float* o = out + (size_t)row * D_MODEL;
    o[t]     = d0 * inv * w[t]     + b[t];
    o[t+256] = d1 * inv * w[t+256] + b[t+256];
}

// ---------------- launch ---------------------------------------------------------
extern "C" void kernel_launch(void* const* d_in, const int* in_sizes, int n_in,
                              void* d_out, int out_size) {
    const float* x     = (const float*)d_in[0];
    const float* W_in  = (const float*)d_in[1];
    const float* b_in  = (const float*)d_in[2];
    const float* W_out = (const float*)d_in[3];
    const float* b_out = (const float*)d_in[4];
    const float* rot   = (const float*)d_in[5];
    const float* ent   = (const float*)d_in[6];
    const float* ln_w  = (const float*)d_in[7];
    const float* ln_b  = (const float*)d_in[8];
    float* out = (float*)d_out;

    float *dv, *Sp, *pre;
    __half *Cs, *xs, *Q, *Wouts;
    cudaGetSymbolAddress((void**)&Cs,    g_Cs);
    cudaGetSymbolAddress((void**)&dv,    g_d);
    cudaGetSymbolAddress((void**)&xs,    g_xs);
    cudaGetSymbolAddress((void**)&Q,     g_Q);
    cudaGetSymbolAddress((void**)&Sp,    g_S);
    cudaGetSymbolAddress((void**)&Wouts, g_Wouts);
    cudaGetSymbolAddress((void**)&pre,   g_pre);

    cudaFuncSetAttribute(gemm_mma<0>, cudaFuncAttributeMaxDynamicSharedMemorySize, SMEM_TOTAL);
    cudaFuncSetAttribute(gemm_mma<1>, cudaFuncAttributeMaxDynamicSharedMemorySize, SMEM_TOTAL);

    // 1) fused prep: circuit sim (Cs, d) + fp16 conversions (xs, Wouts)
    prep_all<<<NSIMB + NCONVB, 256>>>(rot, ent, W_in, b_in, x, W_out,
                                      Cs, dv, xs, Wouts);

    // 2) amp GEMM + fused |amp|^2 epilogue: Q fp16 [16384,1024] + row partials
    gemm_mma<1><<<dim3(2048/BN, N_TOKENS/BM), NTHREADS, SMEM_TOTAL>>>(
        xs, Cs, nullptr, Q, Sp, dv, N_TOKENS, 2048, D_MODEL, D_MODEL);

    // 3) preU = Q @ fp16(W_out)^T (single pass, fp32)
    gemm_mma<0><<<dim3(D_MODEL/BN, N_TOKENS/BM), NTHREADS, SMEM_TOTAL>>>(
        Q, Wouts, pre, nullptr, nullptr, nullptr, N_TOKENS, D_MODEL, DIM, DIM);

    // 4) finalize: pre/s + b_out, LayerNorm
    finalize<<<N_TOKENS, 256>>>(pre, Sp, b_out, ln_w, ln_b, out);
}